// round 16
// baseline (speedup 1.0000x reference)
#include <cuda_runtime.h>
#include <cstdint>
#include <math.h>

#define T_LEN 16384
#define D_IN  2048
#define HID   256
#define G3H   768
#define NCLUS 8
#define FUSED_THREADS 256
#define GEMM_CTAS 3072           // 12 x 128 x 2
#define FUSED_GRID (16 + GEMM_CTAS)

// ---------------- device scratch (static, no allocation) ----------------
__device__ float d_gx[2][(size_t)T_LEN * G3H];   // input projections, both dirs
__device__ float d_h[(size_t)T_LEN * 512];       // concat(h_f, h_b)
__device__ float d_clip[D_IN];
__device__ float d_wts[8];
__device__ int   d_chosen[8];
__device__ float d_c1[256];
__device__ int   d_ready_cnt[2][128];            // monotonic chunk counters

// ---------------- helpers ----------------
union F4U { float4 f4; unsigned long long u[2]; float f[4]; float2 f2[2]; };

#define FMA_F32X2(d, a, b, c) \
    asm("fma.rn.f32x2 %0, %1, %2, %3;" : "=l"(d) : "l"(a), "l"(b), "l"(c))
#define ADD_F32X2_(d, a, b) \
    asm("add.rn.f32x2 %0, %1, %2;" : "=l"(d) : "l"(a), "l"(b))
#define PACKF2(u, x, y) \
    asm("mov.b64 %0, {%1, %2};" : "=l"(u) : "f"(x), "f"(y))

__device__ __forceinline__ float2 u2f2(unsigned long long u) {
    float2 r; asm("mov.b64 {%0, %1}, %2;" : "=f"(r.x), "=f"(r.y) : "l"(u)); return r;
}
__device__ __forceinline__ uint32_t smem_u32(const void* p) {
    return (uint32_t)__cvta_generic_to_shared(p);
}
__device__ __forceinline__ uint32_t mapa_rank(uint32_t addr, uint32_t rank) {
    uint32_t d;
    asm("mapa.shared::cluster.u32 %0, %1, %2;" : "=r"(d) : "r"(addr), "r"(rank));
    return d;
}
__device__ __forceinline__ void mbar_init(uint32_t addr, uint32_t cnt) {
    asm volatile("mbarrier.init.shared.b64 [%0], %1;" :: "r"(addr), "r"(cnt) : "memory");
}
__device__ __forceinline__ void mbar_arrive_local(uint32_t addr) {
    asm volatile("mbarrier.arrive.shared.b64 _, [%0];" :: "r"(addr) : "memory");
}
__device__ __forceinline__ void mbar_arrive_expect_tx(uint32_t addr, uint32_t tx) {
    asm volatile("mbarrier.arrive.expect_tx.shared.b64 _, [%0], %1;"
                 :: "r"(addr), "r"(tx) : "memory");
}
// One-way remote PAIR store with transaction accounting on the TARGET CTA's
// mbarrier: 8 bytes per tx update -> halves mbarrier update traffic.
__device__ __forceinline__ void st_async_cluster_f64(uint32_t daddr, unsigned long long v,
                                                     uint32_t mbar) {
    asm volatile(
        "st.async.shared::cluster.mbarrier::complete_tx::bytes.b64 [%0], %1, [%2];"
        :: "r"(daddr), "l"(v), "r"(mbar) : "memory");
}
__device__ __forceinline__ void mbar_wait_parity_relaxed(uint32_t addr, uint32_t par) {
    asm volatile(
        "{\n\t.reg .pred P;\n\t"
        "W%=:\n\t"
        "mbarrier.try_wait.parity.relaxed.cta.shared::cta.b64 P, [%0], %1, 0x989680;\n\t"
        "@P bra D%=;\n\t"
        "bra W%=;\n\t"
        "D%=:\n\t}"
        :: "r"(addr), "r"(par) : "memory");
}
__device__ __forceinline__ float fast_sigmoid(float x) {
    return __fdividef(1.f, 1.f + __expf(-x));
}
__device__ __forceinline__ float fast_tanh(float x) {
    return __fdividef(2.f, 1.f + __expf(-2.f * x)) - 1.f;
}
// gate the scan's gx consumption on GEMM chunk completion (monotonic cnt)
__device__ __forceinline__ void wait_chunk(int dir, int c) {
    const volatile int* p = &d_ready_cnt[dir][c];
    if (*p < 12) { while (*p < 12) { } }
    __threadfence();
}

// =====================================================================
// FUSED kernel: blocks 0..15 = BiGRU scan clusters (2 clusters of 8),
// blocks 16..3087 = gx GEMM tiles feeding the scan through d_ready_cnt.
// =====================================================================
__global__ void __cluster_dims__(NCLUS, 1, 1) __launch_bounds__(FUSED_THREADS, 1)
fused_kernel(const float* __restrict__ feat,
             const float* __restrict__ Wihf, const float* __restrict__ bihf,
             const float* __restrict__ Wihb, const float* __restrict__ bihb,
             const float* __restrict__ Whf,  const float* __restrict__ bhf,
             const float* __restrict__ Whb,  const float* __restrict__ bhb)
{
    if (blockIdx.x >= 16) {
        // ================== GEMM path ==================
        const int bid = blockIdx.x - 16;
        const int dir = bid / 1536;
        const int rem = bid - dir * 1536;
        const int ox  = rem % 12;
        const int yraw = rem / 12;
        // both-ends-first: forward scan needs low t, backward needs high t
        const int ty = (yraw & 1) ? (127 - (yraw >> 1)) : (yraw >> 1);

        const float* __restrict__ W    = dir ? Wihb : Wihf;
        const float* __restrict__ bias = dir ? bihb : bihf;
        float* __restrict__ C = d_gx[dir];

        const int t0 = ty * 128;
        const int o0 = ox * 64;

        __shared__ float As[16][132];
        __shared__ float Bs[16][68];

        const int tid = threadIdx.x;
        const int tx = tid & 15, tyy = tid >> 4;
        const int m0 = tyy * 8, n0 = tx * 4;

        const int ar0 = tid >> 2;
        const int akq = (tid & 3) * 4;

        const float* aptr0 = feat + (size_t)(t0 + ar0)      * D_IN + akq;
        const float* aptr1 = feat + (size_t)(t0 + ar0 + 64) * D_IN + akq;
        const float* bptr  = W    + (size_t)(o0 + ar0)      * D_IN + akq;

        float4 pa0 = *(const float4*)(aptr0);
        float4 pa1 = *(const float4*)(aptr1);
        float4 pb  = *(const float4*)(bptr);

        unsigned long long acc2[4][4];
#pragma unroll
        for (int i = 0; i < 4; i++)
#pragma unroll
            for (int j = 0; j < 4; j++) acc2[i][j] = 0ull;

        for (int kt = 0; kt < D_IN; kt += 16) {
            As[akq + 0][ar0] = pa0.x; As[akq + 1][ar0] = pa0.y;
            As[akq + 2][ar0] = pa0.z; As[akq + 3][ar0] = pa0.w;
            As[akq + 0][ar0 + 64] = pa1.x; As[akq + 1][ar0 + 64] = pa1.y;
            As[akq + 2][ar0 + 64] = pa1.z; As[akq + 3][ar0 + 64] = pa1.w;
            Bs[akq + 0][ar0] = pb.x; Bs[akq + 1][ar0] = pb.y;
            Bs[akq + 2][ar0] = pb.z; Bs[akq + 3][ar0] = pb.w;
            __syncthreads();

            if (kt + 16 < D_IN) {
                pa0 = *(const float4*)(aptr0 + kt + 16);
                pa1 = *(const float4*)(aptr1 + kt + 16);
                pb  = *(const float4*)(bptr  + kt + 16);
            }

#pragma unroll
            for (int k = 0; k < 16; k++) {
                F4U a0, a1, b;
                a0.f4 = *(const float4*)&As[k][m0];
                a1.f4 = *(const float4*)&As[k][m0 + 4];
                b.f4  = *(const float4*)&Bs[k][n0];
                unsigned long long a2[4] = {a0.u[0], a0.u[1], a1.u[0], a1.u[1]};
                unsigned long long bd[4];
                PACKF2(bd[0], b.f[0], b.f[0]);
                PACKF2(bd[1], b.f[1], b.f[1]);
                PACKF2(bd[2], b.f[2], b.f[2]);
                PACKF2(bd[3], b.f[3], b.f[3]);
#pragma unroll
                for (int i = 0; i < 4; i++)
#pragma unroll
                    for (int j = 0; j < 4; j++)
                        FMA_F32X2(acc2[i][j], a2[i], bd[j], acc2[i][j]);
            }
            __syncthreads();
        }

        const float4 bv4 = *(const float4*)&bias[o0 + n0];
#pragma unroll
        for (int i2 = 0; i2 < 4; i2++) {
            float2 p0 = u2f2(acc2[i2][0]);
            float2 p1 = u2f2(acc2[i2][1]);
            float2 p2 = u2f2(acc2[i2][2]);
            float2 p3 = u2f2(acc2[i2][3]);
            float4 v0, v1;
            v0.x = p0.x + bv4.x; v0.y = p1.x + bv4.y; v0.z = p2.x + bv4.z; v0.w = p3.x + bv4.w;
            v1.x = p0.y + bv4.x; v1.y = p1.y + bv4.y; v1.z = p2.y + bv4.z; v1.w = p3.y + bv4.w;
            *(float4*)&C[(size_t)(t0 + m0 + 2 * i2 + 0) * G3H + o0 + n0] = v0;
            *(float4*)&C[(size_t)(t0 + m0 + 2 * i2 + 1) * G3H + o0 + n0] = v1;
        }

        // publish chunk completion (canonical fence -> sync -> flag)
        __threadfence();
        __syncthreads();
        if (tid == 0) atomicAdd(&d_ready_cnt[dir][ty], 1);
        return;
    }

    // ================== SCAN path ==================
    // padded h: idx(k) = k + (k>>5)*4 ; 8 segs of 32 floats at word 36*seg
    __shared__ __align__(16) float sh_h[2 * 288];
    __shared__ __align__(8) unsigned long long mbars[2];

    const int rank = blockIdx.x & 7;
    const int dir  = blockIdx.x >> 3;
    const float* __restrict__ Whh = dir ? Whb : Whf;
    const float* __restrict__ bhh = dir ? bhb : bhf;
    const float* __restrict__ gx  = d_gx[dir];

    const int tid  = threadIdx.x;
    const int jloc = tid >> 3;         // 0..31 owned hidden unit
    const int seg  = tid & 7;          // 0..7 (32 h each); also target rank
    const int j    = (rank << 5) + jloc;

    // W rows for gates r (row j), z (256+j), n (512+j), this seg's 32 cols
    F4U wr[8], wz[8], wn[8];
    {
        const float4* pr = (const float4*)(Whh + (size_t)(j)       * HID + seg * 32);
        const float4* pz = (const float4*)(Whh + (size_t)(256 + j) * HID + seg * 32);
        const float4* pn = (const float4*)(Whh + (size_t)(512 + j) * HID + seg * 32);
#pragma unroll
        for (int i = 0; i < 8; i++) { wr[i].f4 = pr[i]; wz[i].f4 = pz[i]; wn[i].f4 = pn[i]; }
    }
    const float biasr = bhh[j];
    const float biasz = bhh[256 + j];
    const float biasn = bhh[512 + j];

    for (int i = tid; i < 2 * 288; i += FUSED_THREADS) sh_h[i] = 0.f;
    const uint32_t mb0 = smem_u32(&mbars[0]);
    const uint32_t mb1 = smem_u32(&mbars[1]);
    if (tid == 0) {
        mbar_init(mb0, 1);
        mbar_init(mb1, 1);
        mbar_arrive_local(mb0);   // align parity sequences to ((s+1)>>1)&1
    }
    __syncthreads();
    asm volatile("barrier.cluster.arrive.aligned;" ::: "memory");
    asm volatile("barrier.cluster.wait.aligned;" ::: "memory");

    const float* hs0 = sh_h + 36 * seg;
    const uint32_t hword = (uint32_t)(j + ((j >> 5) << 2));   // padded word idx

    // this lane's pair-store target (even jloc lanes ship {h[j],h[j+1]})
    const uint32_t rh     = mapa_rank(smem_u32(&sh_h[0]), (uint32_t)seg) + hword * 4u;
    const uint32_t rmb[2] = { mapa_rank(mb0, (uint32_t)seg),
                              mapa_rank(mb1, (uint32_t)seg) };
    const uint32_t mbl[2] = { mb0, mb1 };
    const bool isEvenJ = ((jloc & 1) == 0);

    int t = dir ? (T_LEN - 1) : 0;
    const int tstep = dir ? -1 : 1;
    const int entry = dir ? 127 : 0;   // t&127 value on chunk entry
    float hold = 0.f;
    float xr, xz, xn;
    wait_chunk(dir, t >> 7);
    {
        const float* gp = gx + (size_t)t * G3H + j;
        xr = gp[0]; xz = gp[HID]; xn = gp[2 * HID];
    }

#pragma unroll 2
    for (int s = 0; s < T_LEN; s++) {
        const int b = s & 1;

        if (tid == 0) mbar_arrive_expect_tx(mbl[b ^ 1], 8 * 32 * 4);

        // ---- matvec: 3 gate rows x this seg's 32 h (h loads shared) ----
        const float* hp = hs0 + b * 288;
        unsigned long long ar0 = 0ull, ar1 = 0ull, az0 = 0ull, az1 = 0ull,
                           an0 = 0ull, an1 = 0ull;
#pragma unroll
        for (int i = 0; i < 8; i += 2) {
            F4U h0, h1;
            h0.f4 = *(const float4*)(hp + 4 * i);
            h1.f4 = *(const float4*)(hp + 4 * i + 4);
            FMA_F32X2(ar0, wr[i].u[0],     h0.u[0], ar0);
            FMA_F32X2(ar1, wr[i].u[1],     h0.u[1], ar1);
            FMA_F32X2(az0, wz[i].u[0],     h0.u[0], az0);
            FMA_F32X2(az1, wz[i].u[1],     h0.u[1], az1);
            FMA_F32X2(an0, wn[i].u[0],     h0.u[0], an0);
            FMA_F32X2(an1, wn[i].u[1],     h0.u[1], an1);
            FMA_F32X2(ar0, wr[i + 1].u[0], h1.u[0], ar0);
            FMA_F32X2(ar1, wr[i + 1].u[1], h1.u[1], ar1);
            FMA_F32X2(az0, wz[i + 1].u[0], h1.u[0], az0);
            FMA_F32X2(az1, wz[i + 1].u[1], h1.u[1], az1);
            FMA_F32X2(an0, wn[i + 1].u[0], h1.u[0], an0);
            FMA_F32X2(an1, wn[i + 1].u[1], h1.u[1], an1);
        }
        ADD_F32X2_(ar0, ar0, ar1);
        ADD_F32X2_(az0, az0, az1);
        ADD_F32X2_(an0, an0, an1);
        float2 prx = u2f2(ar0), pzx = u2f2(az0), pnx = u2f2(an0);
        float gr = prx.x + prx.y;
        float gz = pzx.x + pzx.y;
        float gn = pnx.x + pnx.y;
#pragma unroll
        for (int d = 4; d; d >>= 1) {
            gr += __shfl_xor_sync(0xffffffffu, gr, d);
            gz += __shfl_xor_sync(0xffffffffu, gz, d);
            gn += __shfl_xor_sync(0xffffffffu, gn, d);
        }

        // ---- gate combine (redundant across the 8 lanes of the group) ----
        const float r = fast_sigmoid(xr + gr + biasr);
        const float z = fast_sigmoid(xz + gz + biasz);
        const float n = fast_tanh(xn + r * (gn + biasn));
        const float hnew = (1.f - z) * n + z * hold;
        hold = hnew;

        // pair up {h[j], h[j+1]}: partner's hnew lives 8 lanes down
        const float hnext = __shfl_down_sync(0xffffffffu, hnew, 8);
        if (isEvenJ) {
            unsigned long long pk;
            PACKF2(pk, hnew, hnext);
            st_async_cluster_f64(rh + (uint32_t)(b ^ 1) * 1152u, pk, rmb[b ^ 1]);
            if (seg == 0)
                *(float2*)&d_h[(size_t)t * 512 + dir * HID + j] = make_float2(hnew, hnext);
        }

        // prefetch gx for next step (gated on producer chunk readiness)
        if (s + 1 < T_LEN) {
            t += tstep;
            if ((t & 127) == entry) wait_chunk(dir, t >> 7);
            const float* gp = gx + (size_t)t * G3H + j;
            xr = gp[0]; xz = gp[HID]; xn = gp[2 * HID];
        }

        mbar_wait_parity_relaxed(mbl[b ^ 1], (uint32_t)(((s + 1) >> 1) & 1));
    }

    asm volatile("barrier.cluster.arrive.aligned;" ::: "memory");
    asm volatile("barrier.cluster.wait.aligned;" ::: "memory");
}

// =====================================================================
// Kernel 3: scores[t] = relu(h[t] @ Ws1^T + bs1) @ Ws2^T + bs2
// =====================================================================
#define SCORES_SMEM_FLOATS (64 * 516 + 64 + 64 + 32 * 512)
__global__ __launch_bounds__(512)
void scores_kernel(const float* __restrict__ Ws1, const float* __restrict__ bs1,
                   const float* __restrict__ Ws2, const float* __restrict__ bs2,
                   float* __restrict__ out)
{
    extern __shared__ float sm[];
    float* sW1 = sm;                  // 64 x 516 (padded, 16B-aligned rows)
    float* sW2 = sm + 64 * 516;       // 64
    float* sb1 = sW2 + 64;            // 64
    float* sh  = sb1 + 64;            // 32 x 512

    const int tid = threadIdx.x;
    for (int i = tid; i < 64 * 512; i += 512) {
        const int kk = i >> 9, jcol = i & 511;
        sW1[kk * 516 + jcol] = Ws1[i];
    }
    if (tid < 64) { sW2[tid] = Ws2[tid]; sb1[tid] = bs1[tid]; }
    const float bs2v = bs2[0];
    __syncthreads();

    const int warp = tid >> 5, lane = tid & 31;
    const float* w0p = sW1 + (size_t)lane * 516;
    const float* w1p = sW1 + (size_t)(lane + 32) * 516;

    for (int iter = 0; iter < 4; iter++) {
        const int r0 = blockIdx.x * 128 + iter * 32;
        __syncthreads();
        for (int e = tid * 4; e < 32 * 512; e += 512 * 4) {
            const int rrow = e >> 9, col = e & 511;
            *(float4*)&sh[e] = *(const float4*)&d_h[(size_t)(r0 + rrow) * 512 + col];
        }
        __syncthreads();

#pragma unroll
        for (int rr = 0; rr < 2; rr++) {
            const int rowl = warp * 2 + rr;
            const float* hrow = sh + (size_t)rowl * 512;
            unsigned long long c00 = 0ull, c01 = 0ull, c10 = 0ull, c11 = 0ull;
            for (int jc = 0; jc < 512; jc += 4) {
                F4U hv, w0v, w1v;
                hv.f4  = *(const float4*)(hrow + jc);
                w0v.f4 = *(const float4*)(w0p + jc);
                w1v.f4 = *(const float4*)(w1p + jc);
                FMA_F32X2(c00, hv.u[0], w0v.u[0], c00);
                FMA_F32X2(c01, hv.u[1], w0v.u[1], c01);
                FMA_F32X2(c10, hv.u[0], w1v.u[0], c10);
                FMA_F32X2(c11, hv.u[1], w1v.u[1], c11);
            }
            ADD_F32X2_(c00, c00, c01);
            ADD_F32X2_(c10, c10, c11);
            float2 s0 = u2f2(c00), s1 = u2f2(c10);
            const float acc0 = s0.x + s0.y;
            const float acc1 = s1.x + s1.y;
            float v = fmaxf(acc0 + sb1[lane], 0.f) * sW2[lane]
                    + fmaxf(acc1 + sb1[lane + 32], 0.f) * sW2[lane + 32];
#pragma unroll
            for (int o = 16; o; o >>= 1) v += __shfl_down_sync(0xffffffffu, v, o);
            if (lane == 0) out[2 + r0 + rowl] = v + bs2v;
        }
    }
}

// =====================================================================
// Kernel 4a: top-8 -> softmax weights -> clip_repr (1 CTA, 1024 thr)
// =====================================================================
__global__ __launch_bounds__(1024)
void topk_clip_kernel(const float* __restrict__ feat, const float* __restrict__ temp,
                      const float* __restrict__ out_scores)
{
    __shared__ float rv[1024];
    __shared__ int   ri[1024];
    __shared__ int   chosen[8];
    __shared__ float chval[8];
    __shared__ float wts[8];

    const float* scores = out_scores + 2;
    const int tid = threadIdx.x;

    float sc[16];
#pragma unroll
    for (int i = 0; i < 16; i++) sc[i] = scores[tid + (i << 10)];
    unsigned taken = 0;

    for (int k = 0; k < 8; k++) {
        float best = -3.4e38f; int bi = 0x7fffffff;
#pragma unroll
        for (int i = 0; i < 16; i++) {
            const int jg = tid + (i << 10);
            const float v = sc[i];
            if (!(taken & (1u << i)) && (v > best || (v == best && jg < bi))) {
                best = v; bi = jg;
            }
        }
        rv[tid] = best; ri[tid] = bi;
        __syncthreads();
        for (int s = 512; s; s >>= 1) {
            if (tid < s) {
                if (rv[tid + s] > rv[tid] ||
                    (rv[tid + s] == rv[tid] && ri[tid + s] < ri[tid])) {
                    rv[tid] = rv[tid + s]; ri[tid] = ri[tid + s];
                }
            }
            __syncthreads();
        }
        if (tid == 0) { chosen[k] = ri[0]; chval[k] = rv[0]; }
        __syncthreads();
        const int ck = chosen[k];
        if ((ck & 1023) == tid) taken |= 1u << (ck >> 10);
    }

    if (tid == 0) {
        const float tmp = temp[0];
        float m = chval[0];
        for (int k = 1; k < 8; k++) m = fmaxf(m, chval[k]);
        float ssum = 0.f;
        for (int k = 0; k < 8; k++) { const float e = expf((chval[k] - m) / tmp); wts[k] = e; ssum += e; }
        for (int k = 0; k < 8; k++) { wts[k] /= ssum; d_wts[k] = wts[k]; d_chosen[k] = chosen[k]; }
    }
    __syncthreads();

    for (int d = tid; d < D_IN; d += 1024) {
        float c = 0.f;
#pragma unroll
        for (int k = 0; k < 8; k++)
            c = fmaf(wts[k], feat[(size_t)chosen[k] * D_IN + d], c);
        d_clip[d] = c;
    }
}

// =====================================================================
// Kernel 4b: c1 = relu(Wc1 @ clip + bc1), 16 CTAs x 256 thr (16 thr/row)
// =====================================================================
__global__ __launch_bounds__(256)
void classify_kernel(const float* __restrict__ Wc1, const float* __restrict__ bc1)
{
    const int tid = threadIdx.x;
    const int o = blockIdx.x * 16 + (tid >> 4);
    const int part = tid & 15;
    const float* wr = Wc1 + (size_t)o * D_IN + part * 128;
    const float* cp = d_clip + part * 128;
    float s0 = 0.f, s1 = 0.f, s2 = 0.f, s3 = 0.f;
#pragma unroll
    for (int jc = 0; jc < 128; jc += 16) {
        const float4 c0 = *(const float4*)(cp + jc);
        const float4 w0 = *(const float4*)(wr + jc);
        const float4 c1v = *(const float4*)(cp + jc + 4);
        const float4 w1 = *(const float4*)(wr + jc + 4);
        const float4 c2 = *(const float4*)(cp + jc + 8);
        const float4 w2 = *(const float4*)(wr + jc + 8);
        const float4 c3 = *(const float4*)(cp + jc + 12);
        const float4 w3 = *(const float4*)(wr + jc + 12);
        s0 = fmaf(c0.x, w0.x, s0); s0 = fmaf(c0.y, w0.y, s0);
        s0 = fmaf(c0.z, w0.z, s0); s0 = fmaf(c0.w, w0.w, s0);
        s1 = fmaf(c1v.x, w1.x, s1); s1 = fmaf(c1v.y, w1.y, s1);
        s1 = fmaf(c1v.z, w1.z, s1); s1 = fmaf(c1v.w, w1.w, s1);
        s2 = fmaf(c2.x, w2.x, s2); s2 = fmaf(c2.y, w2.y, s2);
        s2 = fmaf(c2.z, w2.z, s2); s2 = fmaf(c2.w, w2.w, s2);
        s3 = fmaf(c3.x, w3.x, s3); s3 = fmaf(c3.y, w3.y, s3);
        s3 = fmaf(c3.z, w3.z, s3); s3 = fmaf(c3.w, w3.w, s3);
    }
    float s = (s0 + s1) + (s2 + s3);
    s += __shfl_down_sync(0xffffffffu, s, 8, 16);
    s += __shfl_down_sync(0xffffffffu, s, 4, 16);
    s += __shfl_down_sync(0xffffffffu, s, 2, 16);
    s += __shfl_down_sync(0xffffffffu, s, 1, 16);
    if (part == 0) d_c1[o] = fmaxf(s + bc1[o], 0.f);
}

// =====================================================================
// Kernel 4c: logits = c1 @ Wc2^T + bc2 (1 CTA, 64 thr)
// =====================================================================
__global__ __launch_bounds__(64)
void logits_kernel(const float* __restrict__ Wc2, const float* __restrict__ bc2,
                   float* __restrict__ out)
{
    const int tid = threadIdx.x;
    const int c = tid >> 5, lane = tid & 31;
    float s = 0.f;
    for (int kk = lane; kk < 256; kk += 32)
        s = fmaf(d_c1[kk], Wc2[(size_t)c * 256 + kk], s);
#pragma unroll
    for (int o = 16; o; o >>= 1) s += __shfl_down_sync(0xffffffffu, s, o);
    if (lane == 0) out[c] = s + bc2[c];
}

// =====================================================================
extern "C" void kernel_launch(void* const* d_in, const int* in_sizes, int n_in,
                              void* d_out, int out_size)
{
    const float* feat   = (const float*)d_in[0];
    const float* temp   = (const float*)d_in[1];
    const float* W_ih_f = (const float*)d_in[2];
    const float* W_hh_f = (const float*)d_in[3];
    const float* b_ih_f = (const float*)d_in[4];
    const float* b_hh_f = (const float*)d_in[5];
    const float* W_ih_b = (const float*)d_in[6];
    const float* W_hh_b = (const float*)d_in[7];
    const float* b_ih_b = (const float*)d_in[8];
    const float* b_hh_b = (const float*)d_in[9];
    const float* Ws1    = (const float*)d_in[10];
    const float* bs1    = (const float*)d_in[11];
    const float* Ws2    = (const float*)d_in[12];
    const float* bs2    = (const float*)d_in[13];
    const float* Wc1    = (const float*)d_in[14];
    const float* bc1    = (const float*)d_in[15];
    const float* Wc2    = (const float*)d_in[16];
    const float* bc2    = (const float*)d_in[17];
    float* out = (float*)d_out;

    // 1+2) fused: GEMM producers (3072 CTAs) + BiGRU scan (16 CTAs)
    fused_kernel<<<FUSED_GRID, FUSED_THREADS>>>(
        feat, W_ih_f, b_ih_f, W_ih_b, b_ih_b,
        W_hh_f, b_hh_f, W_hh_b, b_hh_b);

    // 3) frame scores
    cudaFuncSetAttribute(scores_kernel, cudaFuncAttributeMaxDynamicSharedMemorySize,
                         SCORES_SMEM_FLOATS * 4);
    scores_kernel<<<128, 512, SCORES_SMEM_FLOATS * 4>>>(Ws1, bs1, Ws2, bs2, out);

    // 4) top-k + softmax + weighted sum + classifier
    topk_clip_kernel<<<1, 1024>>>(feat, temp, out);
    classify_kernel<<<16, 256>>>(Wc1, bc1);
    logits_kernel<<<1, 64>>>(Wc2, bc2, out);
}

// round 17
// speedup vs baseline: 1.0583x; 1.0583x over previous
#include <cuda_runtime.h>
#include <cstdint>
#include <math.h>

#define T_LEN 16384
#define D_IN  2048
#define HID   256
#define G3H   768
#define NCLUS 8
#define FUSED_THREADS 256
#define GEMM_CTAS 3072           // 2 dirs x 12 x 128
#define FUSED_GRID (16 + GEMM_CTAS)

// ---------------- device scratch (static, no allocation) ----------------
__device__ float d_gx[2][(size_t)T_LEN * G3H];   // input projections, both dirs
__device__ float d_h[(size_t)T_LEN * 512];       // concat(h_f, h_b)
__device__ float d_clip[D_IN];
__device__ float d_wts[8];
__device__ int   d_chosen[8];
__device__ float d_c1[256];
__device__ int   d_ready_cnt[2][128];            // monotonic chunk counters

// ---------------- helpers ----------------
union F4U { float4 f4; unsigned long long u[2]; float f[4]; float2 f2[2]; };

#define FMA_F32X2(d, a, b, c) \
    asm("fma.rn.f32x2 %0, %1, %2, %3;" : "=l"(d) : "l"(a), "l"(b), "l"(c))
#define ADD_F32X2_(d, a, b) \
    asm("add.rn.f32x2 %0, %1, %2;" : "=l"(d) : "l"(a), "l"(b))
#define PACKF2(u, x, y) \
    asm("mov.b64 %0, {%1, %2};" : "=l"(u) : "f"(x), "f"(y))

__device__ __forceinline__ float2 u2f2(unsigned long long u) {
    float2 r; asm("mov.b64 {%0, %1}, %2;" : "=f"(r.x), "=f"(r.y) : "l"(u)); return r;
}
__device__ __forceinline__ uint32_t smem_u32(const void* p) {
    return (uint32_t)__cvta_generic_to_shared(p);
}
__device__ __forceinline__ uint32_t mapa_rank(uint32_t addr, uint32_t rank) {
    uint32_t d;
    asm("mapa.shared::cluster.u32 %0, %1, %2;" : "=r"(d) : "r"(addr), "r"(rank));
    return d;
}
__device__ __forceinline__ void mbar_init(uint32_t addr, uint32_t cnt) {
    asm volatile("mbarrier.init.shared.b64 [%0], %1;" :: "r"(addr), "r"(cnt) : "memory");
}
__device__ __forceinline__ void mbar_arrive_local(uint32_t addr) {
    asm volatile("mbarrier.arrive.shared.b64 _, [%0];" :: "r"(addr) : "memory");
}
__device__ __forceinline__ void mbar_arrive_expect_tx(uint32_t addr, uint32_t tx) {
    asm volatile("mbarrier.arrive.expect_tx.shared.b64 _, [%0], %1;"
                 :: "r"(addr), "r"(tx) : "memory");
}
// One-way remote store with transaction accounting on the TARGET CTA's
// mbarrier: data lands + tx-count updated atomically by HW. (R15-proven.)
__device__ __forceinline__ void st_async_cluster_f32(uint32_t daddr, float v, uint32_t mbar) {
    asm volatile(
        "st.async.shared::cluster.mbarrier::complete_tx::bytes.b32 [%0], %1, [%2];"
        :: "r"(daddr), "r"(__float_as_uint(v)), "r"(mbar) : "memory");
}
__device__ __forceinline__ void mbar_wait_parity_relaxed(uint32_t addr, uint32_t par) {
    asm volatile(
        "{\n\t.reg .pred P;\n\t"
        "W%=:\n\t"
        "mbarrier.try_wait.parity.relaxed.cta.shared::cta.b64 P, [%0], %1, 0x989680;\n\t"
        "@P bra D%=;\n\t"
        "bra W%=;\n\t"
        "D%=:\n\t}"
        :: "r"(addr), "r"(par) : "memory");
}
__device__ __forceinline__ float fast_sigmoid(float x) {
    return __fdividef(1.f, 1.f + __expf(-x));
}
__device__ __forceinline__ float fast_tanh(float x) {
    return __fdividef(2.f, 1.f + __expf(-2.f * x)) - 1.f;
}
// gate the scan's gx consumption on GEMM chunk completion (monotonic cnt)
__device__ __forceinline__ void wait_chunk(int dir, int c) {
    const volatile int* p = &d_ready_cnt[dir][c];
    if (*p < 12) { while (*p < 12) { } }
    __threadfence();
}

// =====================================================================
// FUSED kernel: blocks 0..15 = BiGRU scan clusters (2 clusters of 8),
// blocks 16..3087 = gx GEMM tiles feeding the scan through d_ready_cnt.
// GEMM bid mapping interleaves DIRECTION first (dir = bid&1) and orders
// each dir's t-tiles to match its scan's consumption order, so BOTH
// scans have producer chunks within the first GEMM wave (~70us) instead
// of the backward scan stalling ~0.7ms for dir=1 tiles.
// =====================================================================
__global__ void __cluster_dims__(NCLUS, 1, 1) __launch_bounds__(FUSED_THREADS, 1)
fused_kernel(const float* __restrict__ feat,
             const float* __restrict__ Wihf, const float* __restrict__ bihf,
             const float* __restrict__ Wihb, const float* __restrict__ bihb,
             const float* __restrict__ Whf,  const float* __restrict__ bhf,
             const float* __restrict__ Whb,  const float* __restrict__ bhb)
{
    if (blockIdx.x >= 16) {
        // ================== GEMM path ==================
        const int bid = blockIdx.x - 16;
        const int dir = bid & 1;                 // interleave dirs across waves
        const int rem = bid >> 1;                // 0..1535
        const int ox  = rem % 12;
        const int tyi = rem / 12;                // 0..127 in consumption order
        const int ty  = dir ? (127 - tyi) : tyi; // fwd ascending, bwd descending

        const float* __restrict__ W    = dir ? Wihb : Wihf;
        const float* __restrict__ bias = dir ? bihb : bihf;
        float* __restrict__ C = d_gx[dir];

        const int t0 = ty * 128;
        const int o0 = ox * 64;

        __shared__ float As[16][132];
        __shared__ float Bs[16][68];

        const int tid = threadIdx.x;
        const int tx = tid & 15, tyy = tid >> 4;
        const int m0 = tyy * 8, n0 = tx * 4;

        const int ar0 = tid >> 2;
        const int akq = (tid & 3) * 4;

        const float* aptr0 = feat + (size_t)(t0 + ar0)      * D_IN + akq;
        const float* aptr1 = feat + (size_t)(t0 + ar0 + 64) * D_IN + akq;
        const float* bptr  = W    + (size_t)(o0 + ar0)      * D_IN + akq;

        float4 pa0 = *(const float4*)(aptr0);
        float4 pa1 = *(const float4*)(aptr1);
        float4 pb  = *(const float4*)(bptr);

        unsigned long long acc2[4][4];
#pragma unroll
        for (int i = 0; i < 4; i++)
#pragma unroll
            for (int j = 0; j < 4; j++) acc2[i][j] = 0ull;

        for (int kt = 0; kt < D_IN; kt += 16) {
            As[akq + 0][ar0] = pa0.x; As[akq + 1][ar0] = pa0.y;
            As[akq + 2][ar0] = pa0.z; As[akq + 3][ar0] = pa0.w;
            As[akq + 0][ar0 + 64] = pa1.x; As[akq + 1][ar0 + 64] = pa1.y;
            As[akq + 2][ar0 + 64] = pa1.z; As[akq + 3][ar0 + 64] = pa1.w;
            Bs[akq + 0][ar0] = pb.x; Bs[akq + 1][ar0] = pb.y;
            Bs[akq + 2][ar0] = pb.z; Bs[akq + 3][ar0] = pb.w;
            __syncthreads();

            if (kt + 16 < D_IN) {
                pa0 = *(const float4*)(aptr0 + kt + 16);
                pa1 = *(const float4*)(aptr1 + kt + 16);
                pb  = *(const float4*)(bptr  + kt + 16);
            }

#pragma unroll
            for (int k = 0; k < 16; k++) {
                F4U a0, a1, b;
                a0.f4 = *(const float4*)&As[k][m0];
                a1.f4 = *(const float4*)&As[k][m0 + 4];
                b.f4  = *(const float4*)&Bs[k][n0];
                unsigned long long a2[4] = {a0.u[0], a0.u[1], a1.u[0], a1.u[1]};
                unsigned long long bd[4];
                PACKF2(bd[0], b.f[0], b.f[0]);
                PACKF2(bd[1], b.f[1], b.f[1]);
                PACKF2(bd[2], b.f[2], b.f[2]);
                PACKF2(bd[3], b.f[3], b.f[3]);
#pragma unroll
                for (int i = 0; i < 4; i++)
#pragma unroll
                    for (int j = 0; j < 4; j++)
                        FMA_F32X2(acc2[i][j], a2[i], bd[j], acc2[i][j]);
            }
            __syncthreads();
        }

        const float4 bv4 = *(const float4*)&bias[o0 + n0];
#pragma unroll
        for (int i2 = 0; i2 < 4; i2++) {
            float2 p0 = u2f2(acc2[i2][0]);
            float2 p1 = u2f2(acc2[i2][1]);
            float2 p2 = u2f2(acc2[i2][2]);
            float2 p3 = u2f2(acc2[i2][3]);
            float4 v0, v1;
            v0.x = p0.x + bv4.x; v0.y = p1.x + bv4.y; v0.z = p2.x + bv4.z; v0.w = p3.x + bv4.w;
            v1.x = p0.y + bv4.x; v1.y = p1.y + bv4.y; v1.z = p2.y + bv4.z; v1.w = p3.y + bv4.w;
            *(float4*)&C[(size_t)(t0 + m0 + 2 * i2 + 0) * G3H + o0 + n0] = v0;
            *(float4*)&C[(size_t)(t0 + m0 + 2 * i2 + 1) * G3H + o0 + n0] = v1;
        }

        // publish chunk completion (canonical fence -> sync -> flag)
        __threadfence();
        __syncthreads();
        if (tid == 0) atomicAdd(&d_ready_cnt[dir][ty], 1);
        return;
    }

    // ================== SCAN path (R15-proven) ==================
    // padded h: idx(k) = k + (k>>5)*4 ; 8 segs of 32 floats at word 36*seg
    __shared__ __align__(16) float sh_h[2 * 288];
    __shared__ __align__(8) unsigned long long mbars[2];

    const int rank = blockIdx.x & 7;
    const int dir  = blockIdx.x >> 3;
    const float* __restrict__ Whh = dir ? Whb : Whf;
    const float* __restrict__ bhh = dir ? bhb : bhf;
    const float* __restrict__ gx  = d_gx[dir];

    const int tid  = threadIdx.x;
    const int jloc = tid >> 3;         // 0..31 owned hidden unit
    const int seg  = tid & 7;          // 0..7 (32 h each); also target rank
    const int j    = (rank << 5) + jloc;

    // W rows for gates r (row j), z (256+j), n (512+j), this seg's 32 cols
    F4U wr[8], wz[8], wn[8];
    {
        const float4* pr = (const float4*)(Whh + (size_t)(j)       * HID + seg * 32);
        const float4* pz = (const float4*)(Whh + (size_t)(256 + j) * HID + seg * 32);
        const float4* pn = (const float4*)(Whh + (size_t)(512 + j) * HID + seg * 32);
#pragma unroll
        for (int i = 0; i < 8; i++) { wr[i].f4 = pr[i]; wz[i].f4 = pz[i]; wn[i].f4 = pn[i]; }
    }
    const float biasr = bhh[j];
    const float biasz = bhh[256 + j];
    const float biasn = bhh[512 + j];

    for (int i = tid; i < 2 * 288; i += FUSED_THREADS) sh_h[i] = 0.f;
    const uint32_t mb0 = smem_u32(&mbars[0]);
    const uint32_t mb1 = smem_u32(&mbars[1]);
    if (tid == 0) {
        mbar_init(mb0, 1);
        mbar_init(mb1, 1);
        mbar_arrive_local(mb0);   // align parity sequences to ((s+1)>>1)&1
    }
    __syncthreads();
    asm volatile("barrier.cluster.arrive.aligned;" ::: "memory");
    asm volatile("barrier.cluster.wait.aligned;" ::: "memory");

    const float* hs0 = sh_h + 36 * seg;
    const uint32_t hword = (uint32_t)(j + ((j >> 5) << 2));   // padded word idx

    const uint32_t rh     = mapa_rank(smem_u32(&sh_h[0]), (uint32_t)seg) + hword * 4u;
    const uint32_t rmb[2] = { mapa_rank(mb0, (uint32_t)seg),
                              mapa_rank(mb1, (uint32_t)seg) };
    const uint32_t mbl[2] = { mb0, mb1 };

    int t = dir ? (T_LEN - 1) : 0;
    const int tstep = dir ? -1 : 1;
    const int entry = dir ? 127 : 0;   // t&127 value on chunk entry
    float hold = 0.f;
    float xr, xz, xn;
    wait_chunk(dir, t >> 7);
    {
        const float* gp = gx + (size_t)t * G3H + j;
        xr = gp[0]; xz = gp[HID]; xn = gp[2 * HID];
    }

#pragma unroll 2
    for (int s = 0; s < T_LEN; s++) {
        const int b = s & 1;

        if (tid == 0) mbar_arrive_expect_tx(mbl[b ^ 1], 8 * 32 * 4);

        // ---- matvec: 3 gate rows x this seg's 32 h (h loads shared) ----
        const float* hp = hs0 + b * 288;
        unsigned long long ar0 = 0ull, ar1 = 0ull, az0 = 0ull, az1 = 0ull,
                           an0 = 0ull, an1 = 0ull;
#pragma unroll
        for (int i = 0; i < 8; i += 2) {
            F4U h0, h1;
            h0.f4 = *(const float4*)(hp + 4 * i);
            h1.f4 = *(const float4*)(hp + 4 * i + 4);
            FMA_F32X2(ar0, wr[i].u[0],     h0.u[0], ar0);
            FMA_F32X2(ar1, wr[i].u[1],     h0.u[1], ar1);
            FMA_F32X2(az0, wz[i].u[0],     h0.u[0], az0);
            FMA_F32X2(az1, wz[i].u[1],     h0.u[1], az1);
            FMA_F32X2(an0, wn[i].u[0],     h0.u[0], an0);
            FMA_F32X2(an1, wn[i].u[1],     h0.u[1], an1);
            FMA_F32X2(ar0, wr[i + 1].u[0], h1.u[0], ar0);
            FMA_F32X2(ar1, wr[i + 1].u[1], h1.u[1], ar1);
            FMA_F32X2(az0, wz[i + 1].u[0], h1.u[0], az0);
            FMA_F32X2(az1, wz[i + 1].u[1], h1.u[1], az1);
            FMA_F32X2(an0, wn[i + 1].u[0], h1.u[0], an0);
            FMA_F32X2(an1, wn[i + 1].u[1], h1.u[1], an1);
        }
        ADD_F32X2_(ar0, ar0, ar1);
        ADD_F32X2_(az0, az0, az1);
        ADD_F32X2_(an0, an0, an1);
        float2 prx = u2f2(ar0), pzx = u2f2(az0), pnx = u2f2(an0);
        float gr = prx.x + prx.y;
        float gz = pzx.x + pzx.y;
        float gn = pnx.x + pnx.y;
#pragma unroll
        for (int d = 4; d; d >>= 1) {
            gr += __shfl_xor_sync(0xffffffffu, gr, d);
            gz += __shfl_xor_sync(0xffffffffu, gz, d);
            gn += __shfl_xor_sync(0xffffffffu, gn, d);
        }

        // ---- gate combine (redundant across the 8 lanes of the group) ----
        const float r = fast_sigmoid(xr + gr + biasr);
        const float z = fast_sigmoid(xz + gz + biasz);
        const float n = fast_tanh(xn + r * (gn + biasn));
        const float hnew = (1.f - z) * n + z * hold;
        hold = hnew;

        st_async_cluster_f32(rh + (uint32_t)(b ^ 1) * 1152u, hnew, rmb[b ^ 1]);
        if (seg == 0) d_h[(size_t)t * 512 + dir * HID + j] = hnew;

        // prefetch gx for next step (gated on producer chunk readiness)
        if (s + 1 < T_LEN) {
            t += tstep;
            if ((t & 127) == entry) wait_chunk(dir, t >> 7);
            const float* gp = gx + (size_t)t * G3H + j;
            xr = gp[0]; xz = gp[HID]; xn = gp[2 * HID];
        }

        mbar_wait_parity_relaxed(mbl[b ^ 1], (uint32_t)(((s + 1) >> 1) & 1));
    }

    asm volatile("barrier.cluster.arrive.aligned;" ::: "memory");
    asm volatile("barrier.cluster.wait.aligned;" ::: "memory");
}

// =====================================================================
// Kernel 3: scores[t] = relu(h[t] @ Ws1^T + bs1) @ Ws2^T + bs2
// =====================================================================
#define SCORES_SMEM_FLOATS (64 * 516 + 64 + 64 + 32 * 512)
__global__ __launch_bounds__(512)
void scores_kernel(const float* __restrict__ Ws1, const float* __restrict__ bs1,
                   const float* __restrict__ Ws2, const float* __restrict__ bs2,
                   float* __restrict__ out)
{
    extern __shared__ float sm[];
    float* sW1 = sm;                  // 64 x 516 (padded, 16B-aligned rows)
    float* sW2 = sm + 64 * 516;       // 64
    float* sb1 = sW2 + 64;            // 64
    float* sh  = sb1 + 64;            // 32 x 512

    const int tid = threadIdx.x;
    for (int i = tid; i < 64 * 512; i += 512) {
        const int kk = i >> 9, jcol = i & 511;
        sW1[kk * 516 + jcol] = Ws1[i];
    }
    if (tid < 64) { sW2[tid] = Ws2[tid]; sb1[tid] = bs1[tid]; }
    const float bs2v = bs2[0];
    __syncthreads();

    const int warp = tid >> 5, lane = tid & 31;
    const float* w0p = sW1 + (size_t)lane * 516;
    const float* w1p = sW1 + (size_t)(lane + 32) * 516;

    for (int iter = 0; iter < 4; iter++) {
        const int r0 = blockIdx.x * 128 + iter * 32;
        __syncthreads();
        for (int e = tid * 4; e < 32 * 512; e += 512 * 4) {
            const int rrow = e >> 9, col = e & 511;
            *(float4*)&sh[e] = *(const float4*)&d_h[(size_t)(r0 + rrow) * 512 + col];
        }
        __syncthreads();

#pragma unroll
        for (int rr = 0; rr < 2; rr++) {
            const int rowl = warp * 2 + rr;
            const float* hrow = sh + (size_t)rowl * 512;
            unsigned long long c00 = 0ull, c01 = 0ull, c10 = 0ull, c11 = 0ull;
            for (int jc = 0; jc < 512; jc += 4) {
                F4U hv, w0v, w1v;
                hv.f4  = *(const float4*)(hrow + jc);
                w0v.f4 = *(const float4*)(w0p + jc);
                w1v.f4 = *(const float4*)(w1p + jc);
                FMA_F32X2(c00, hv.u[0], w0v.u[0], c00);
                FMA_F32X2(c01, hv.u[1], w0v.u[1], c01);
                FMA_F32X2(c10, hv.u[0], w1v.u[0], c10);
                FMA_F32X2(c11, hv.u[1], w1v.u[1], c11);
            }
            ADD_F32X2_(c00, c00, c01);
            ADD_F32X2_(c10, c10, c11);
            float2 s0 = u2f2(c00), s1 = u2f2(c10);
            const float acc0 = s0.x + s0.y;
            const float acc1 = s1.x + s1.y;
            float v = fmaxf(acc0 + sb1[lane], 0.f) * sW2[lane]
                    + fmaxf(acc1 + sb1[lane + 32], 0.f) * sW2[lane + 32];
#pragma unroll
            for (int o = 16; o; o >>= 1) v += __shfl_down_sync(0xffffffffu, v, o);
            if (lane == 0) out[2 + r0 + rowl] = v + bs2v;
        }
    }
}

// =====================================================================
// Kernel 4a: top-8 -> softmax weights -> clip_repr (1 CTA, 1024 thr)
// =====================================================================
__global__ __launch_bounds__(1024)
void topk_clip_kernel(const float* __restrict__ feat, const float* __restrict__ temp,
                      const float* __restrict__ out_scores)
{
    __shared__ float rv[1024];
    __shared__ int   ri[1024];
    __shared__ int   chosen[8];
    __shared__ float chval[8];
    __shared__ float wts[8];

    const float* scores = out_scores + 2;
    const int tid = threadIdx.x;

    float sc[16];
#pragma unroll
    for (int i = 0; i < 16; i++) sc[i] = scores[tid + (i << 10)];
    unsigned taken = 0;

    for (int k = 0; k < 8; k++) {
        float best = -3.4e38f; int bi = 0x7fffffff;
#pragma unroll
        for (int i = 0; i < 16; i++) {
            const int jg = tid + (i << 10);
            const float v = sc[i];
            if (!(taken & (1u << i)) && (v > best || (v == best && jg < bi))) {
                best = v; bi = jg;
            }
        }
        rv[tid] = best; ri[tid] = bi;
        __syncthreads();
        for (int s = 512; s; s >>= 1) {
            if (tid < s) {
                if (rv[tid + s] > rv[tid] ||
                    (rv[tid + s] == rv[tid] && ri[tid + s] < ri[tid])) {
                    rv[tid] = rv[tid + s]; ri[tid] = ri[tid + s];
                }
            }
            __syncthreads();
        }
        if (tid == 0) { chosen[k] = ri[0]; chval[k] = rv[0]; }
        __syncthreads();
        const int ck = chosen[k];
        if ((ck & 1023) == tid) taken |= 1u << (ck >> 10);
    }

    if (tid == 0) {
        const float tmp = temp[0];
        float m = chval[0];
        for (int k = 1; k < 8; k++) m = fmaxf(m, chval[k]);
        float ssum = 0.f;
        for (int k = 0; k < 8; k++) { const float e = expf((chval[k] - m) / tmp); wts[k] = e; ssum += e; }
        for (int k = 0; k < 8; k++) { wts[k] /= ssum; d_wts[k] = wts[k]; d_chosen[k] = chosen[k]; }
    }
    __syncthreads();

    for (int d = tid; d < D_IN; d += 1024) {
        float c = 0.f;
#pragma unroll
        for (int k = 0; k < 8; k++)
            c = fmaf(wts[k], feat[(size_t)chosen[k] * D_IN + d], c);
        d_clip[d] = c;
    }
}

// =====================================================================
// Kernel 4b: c1 = relu(Wc1 @ clip + bc1), 16 CTAs x 256 thr (16 thr/row)
// =====================================================================
__global__ __launch_bounds__(256)
void classify_kernel(const float* __restrict__ Wc1, const float* __restrict__ bc1)
{
    const int tid = threadIdx.x;
    const int o = blockIdx.x * 16 + (tid >> 4);
    const int part = tid & 15;
    const float* wr = Wc1 + (size_t)o * D_IN + part * 128;
    const float* cp = d_clip + part * 128;
    float s0 = 0.f, s1 = 0.f, s2 = 0.f, s3 = 0.f;
#pragma unroll
    for (int jc = 0; jc < 128; jc += 16) {
        const float4 c0 = *(const float4*)(cp + jc);
        const float4 w0 = *(const float4*)(wr + jc);
        const float4 c1v = *(const float4*)(cp + jc + 4);
        const float4 w1 = *(const float4*)(wr + jc + 4);
        const float4 c2 = *(const float4*)(cp + jc + 8);
        const float4 w2 = *(const float4*)(wr + jc + 8);
        const float4 c3 = *(const float4*)(cp + jc + 12);
        const float4 w3 = *(const float4*)(wr + jc + 12);
        s0 = fmaf(c0.x, w0.x, s0); s0 = fmaf(c0.y, w0.y, s0);
        s0 = fmaf(c0.z, w0.z, s0); s0 = fmaf(c0.w, w0.w, s0);
        s1 = fmaf(c1v.x, w1.x, s1); s1 = fmaf(c1v.y, w1.y, s1);
        s1 = fmaf(c1v.z, w1.z, s1); s1 = fmaf(c1v.w, w1.w, s1);
        s2 = fmaf(c2.x, w2.x, s2); s2 = fmaf(c2.y, w2.y, s2);
        s2 = fmaf(c2.z, w2.z, s2); s2 = fmaf(c2.w, w2.w, s2);
        s3 = fmaf(c3.x, w3.x, s3); s3 = fmaf(c3.y, w3.y, s3);
        s3 = fmaf(c3.z, w3.z, s3); s3 = fmaf(c3.w, w3.w, s3);
    }
    float s = (s0 + s1) + (s2 + s3);
    s += __shfl_down_sync(0xffffffffu, s, 8, 16);
    s += __shfl_down_sync(0xffffffffu, s, 4, 16);
    s += __shfl_down_sync(0xffffffffu, s, 2, 16);
    s += __shfl_down_sync(0xffffffffu, s, 1, 16);
    if (part == 0) d_c1[o] = fmaxf(s + bc1[o], 0.f);
}

// =====================================================================
// Kernel 4c: logits = c1 @ Wc2^T + bc2 (1 CTA, 64 thr)
// =====================================================================
__global__ __launch_bounds__(64)
void logits_kernel(const float* __restrict__ Wc2, const float* __restrict__ bc2,
                   float* __restrict__ out)
{
    const int tid = threadIdx.x;
    const int c = tid >> 5, lane = tid & 31;
    float s = 0.f;
    for (int kk = lane; kk < 256; kk += 32)
        s = fmaf(d_c1[kk], Wc2[(size_t)c * 256 + kk], s);
#pragma unroll
    for (int o = 16; o; o >>= 1) s += __shfl_down_sync(0xffffffffu, s, o);
    if (lane == 0) out[c] = s + bc2[c];
}

// =====================================================================
extern "C" void kernel_launch(void* const* d_in, const int* in_sizes, int n_in,
                              void* d_out, int out_size)
{
    const float* feat   = (const float*)d_in[0];
    const float* temp   = (const float*)d_in[1];
    const float* W_ih_f = (const float*)d_in[2];
    const float* W_hh_f = (const float*)d_in[3];
    const float* b_ih_f = (const float*)d_in[4];
    const float* b_hh_f = (const float*)d_in[5];
    const float* W_ih_b = (const float*)d_in[6];
    const float* W_hh_b = (const float*)d_in[7];
    const float* b_ih_b = (const float*)d_in[8];
    const float* b_hh_b = (const float*)d_in[9];
    const float* Ws1    = (const float*)d_in[10];
    const float* bs1    = (const float*)d_in[11];
    const float* Ws2    = (const float*)d_in[12];
    const float* bs2    = (const float*)d_in[13];
    const float* Wc1    = (const float*)d_in[14];
    const float* bc1    = (const float*)d_in[15];
    const float* Wc2    = (const float*)d_in[16];
    const float* bc2    = (const float*)d_in[17];
    float* out = (float*)d_out;

    // 1+2) fused: GEMM producers (3072 CTAs) + BiGRU scan (16 CTAs)
    fused_kernel<<<FUSED_GRID, FUSED_THREADS>>>(
        feat, W_ih_f, b_ih_f, W_ih_b, b_ih_b,
        W_hh_f, b_hh_f, W_hh_b, b_hh_b);

    // 3) frame scores
    cudaFuncSetAttribute(scores_kernel, cudaFuncAttributeMaxDynamicSharedMemorySize,
                         SCORES_SMEM_FLOATS * 4);
    scores_kernel<<<128, 512, SCORES_SMEM_FLOATS * 4>>>(Ws1, bs1, Ws2, bs2, out);

    // 4) top-k + softmax + weighted sum + classifier
    topk_clip_kernel<<<1, 1024>>>(feat, temp, out);
    classify_kernel<<<16, 256>>>(Wc1, bc1);
    logits_kernel<<<1, 64>>>(Wc2, bc2, out);
}